// round 2
// baseline (speedup 1.0000x reference)
#include <cuda_runtime.h>
#include <cstdint>

#define KS   9
#define HID  128
#define LEN  2048
#define ROWS 512   // B*H = 8*64
#define TPB  256
#define TPT  8     // outputs per thread

// ---- packed f32x2 helpers (sm_103a) ----
__device__ __forceinline__ unsigned long long pack2(float lo, float hi) {
    unsigned long long r;
    asm("mov.b64 %0, {%1,%2};" : "=l"(r) : "f"(lo), "f"(hi));
    return r;
}
__device__ __forceinline__ void unpack2(unsigned long long v, float& lo, float& hi) {
    asm("mov.b64 {%0,%1}, %2;" : "=f"(lo), "=f"(hi) : "l"(v));
}
__device__ __forceinline__ unsigned long long fma2(unsigned long long a,
                                                   unsigned long long b,
                                                   unsigned long long c) {
    unsigned long long d;
    asm("fma.rn.f32x2 %0, %1, %2, %3;" : "=l"(d) : "l"(a), "l"(b), "l"(c));
    return d;
}

__global__ __launch_bounds__(TPB)
void simconv1d_kernel(const float* __restrict__ x,
                      const float* __restrict__ W1,   // [9][128] (k, d)
                      const float* __restrict__ b1,   // [128]
                      const float* __restrict__ W2,   // [128]
                      const float* __restrict__ b2,   // [1]
                      float* __restrict__ y) {
    // Per-d packed operands, pre-duplicated: slots 0..8 = W1[k][d] dup'd,
    // slot 9 = b1[d] dup'd. 10 x 8B per d = 10 KB total.
    __shared__ unsigned long long sW1p[HID][10];
    __shared__ float sW2[HID];

    const int tid = threadIdx.x;

    for (int i = tid; i < KS * HID; i += TPB) {
        int k = i / HID;
        int d = i - k * HID;
        float w = W1[i];
        sW1p[d][k] = pack2(w, w);
    }
    if (tid < HID) {
        float b = b1[tid];
        sW1p[tid][9] = pack2(b, b);
        sW2[tid] = W2[tid];
    }
    __syncthreads();

    const int row = blockIdx.x;            // (b*H + h)
    const float* xr = x + row * LEN;
    const int t0 = tid * TPT;              // first output position of this thread

    // Load the 16 x values covering outputs [t0, t0+8) with taps o-4..o+4.
    float xv[TPT + KS - 1];                // 16
    #pragma unroll
    for (int i = 0; i < TPT + KS - 1; i++) {
        int gi = t0 - 4 + i;
        xv[i] = (gi >= 0 && gi < LEN) ? __ldg(xr + gi) : 0.f;
    }

    // Pre-pack overlapping adjacent pairs: xp[i] = (xv[i], xv[i+1])
    unsigned long long xp[TPT + KS - 2];   // 15
    #pragma unroll
    for (int i = 0; i < TPT + KS - 2; i++) xp[i] = pack2(xv[i], xv[i + 1]);

    float acc[TPT];
    #pragma unroll
    for (int t = 0; t < TPT; t++) acc[t] = 0.f;

    const float bias2 = b2[0];

    #pragma unroll 2
    for (int d = 0; d < HID; d++) {
        // broadcast LDS.64 loads: all lanes read same address -> conflict-free
        unsigned long long wk2[KS];
        #pragma unroll
        for (int k = 0; k < KS; k++) wk2[k] = sW1p[d][k];
        unsigned long long bd2 = sW1p[d][9];
        float w2 = sW2[d];

        // 4 independent packed 9-deep FMA chains (good ILP)
        #pragma unroll
        for (int p = 0; p < TPT / 2; p++) {
            unsigned long long h2 = bd2;
            #pragma unroll
            for (int k = 0; k < KS; k++)
                h2 = fma2(xp[2 * p + k], wk2[k], h2);
            float h0, h1;
            unpack2(h2, h0, h1);
            acc[2 * p]     = fmaf(fmaxf(h0, 0.f), w2, acc[2 * p]);
            acc[2 * p + 1] = fmaf(fmaxf(h1, 0.f), w2, acc[2 * p + 1]);
        }
    }

    float* yr = y + row * LEN + t0;
    #pragma unroll
    for (int t = 0; t < TPT; t++) yr[t] = acc[t] + bias2;
}

extern "C" void kernel_launch(void* const* d_in, const int* in_sizes, int n_in,
                              void* d_out, int out_size) {
    const float* x  = (const float*)d_in[0];
    const float* W1 = (const float*)d_in[1];
    const float* b1 = (const float*)d_in[2];
    const float* W2 = (const float*)d_in[3];
    const float* b2 = (const float*)d_in[4];
    float* y = (float*)d_out;
    simconv1d_kernel<<<ROWS, TPB>>>(x, W1, b1, W2, b2, y);
}

// round 3
// speedup vs baseline: 1.2114x; 1.2114x over previous
#include <cuda_runtime.h>
#include <cstdint>

#define KS   9
#define HID  128
#define LEN  2048
#define ROWS 512       // B*H = 8*64
#define TPB  128
#define TPT  8         // outputs per thread
#define HALF_LEN 1024  // outputs per block (half a row)

// ---- packed f32x2 helpers (sm_103a) ----
__device__ __forceinline__ unsigned long long pack2(float lo, float hi) {
    unsigned long long r;
    asm("mov.b64 %0, {%1,%2};" : "=l"(r) : "f"(lo), "f"(hi));
    return r;
}
__device__ __forceinline__ void unpack2(unsigned long long v, float& lo, float& hi) {
    asm("mov.b64 {%0,%1}, %2;" : "=f"(lo), "=f"(hi) : "l"(v));
}
__device__ __forceinline__ unsigned long long fma2(unsigned long long a,
                                                   unsigned long long b,
                                                   unsigned long long c) {
    unsigned long long d;
    asm("fma.rn.f32x2 %0, %1, %2, %3;" : "=l"(d) : "l"(a), "l"(b), "l"(c));
    return d;
}

__global__ __launch_bounds__(TPB, 6)
void simconv1d_kernel(const float* __restrict__ x,
                      const float* __restrict__ W1,   // [9][128] (k, d)
                      const float* __restrict__ b1,   // [128]
                      const float* __restrict__ W2,   // [128]
                      const float* __restrict__ b2,   // [1]
                      float* __restrict__ y) {
    // Per-d packed operands, 16B-aligned for LDS.128:
    // sP[d] = 5 ulonglong2 = slots {w0,w1},{w2,w3},{w4,w5},{w6,w7},{w8,bias}
    __shared__ ulonglong2 sP[HID][5];
    __shared__ float sW2[HID];

    unsigned long long* sPu = reinterpret_cast<unsigned long long*>(sP);
    const int tid = threadIdx.x;

    for (int i = tid; i < KS * HID; i += TPB) {
        int k = i / HID;            // 0..8
        int d = i - k * HID;
        float w = W1[i];
        sPu[d * 10 + k] = pack2(w, w);
    }
    if (tid < HID) {
        float b = b1[tid];
        sPu[tid * 10 + 9] = pack2(b, b);
        sW2[tid] = W2[tid];
    }
    __syncthreads();

    const int row  = blockIdx.x >> 1;
    const int half = blockIdx.x & 1;
    const float* xr = x + row * LEN;
    const int t0 = half * HALF_LEN + tid * TPT;   // first output position

    // Load the 16 x values covering outputs [t0, t0+8) with taps o-4..o+4.
    float xv[TPT + KS - 1];                // 16
    #pragma unroll
    for (int i = 0; i < TPT + KS - 1; i++) {
        int gi = t0 - 4 + i;
        xv[i] = (gi >= 0 && gi < LEN) ? __ldg(xr + gi) : 0.f;
    }

    // Pre-pack overlapping adjacent pairs: xp[i] = (xv[i], xv[i+1])
    unsigned long long xp[TPT + KS - 2];   // 15
    #pragma unroll
    for (int i = 0; i < TPT + KS - 2; i++) xp[i] = pack2(xv[i], xv[i + 1]);

    float acc[TPT];
    #pragma unroll
    for (int t = 0; t < TPT; t++) acc[t] = 0.f;

    const float bias2 = b2[0];

    #pragma unroll 2
    for (int d = 0; d < HID; d++) {
        // 5 broadcast LDS.128 (conflict-free) deliver all 9 weights + bias
        ulonglong2 p0 = sP[d][0];
        ulonglong2 p1 = sP[d][1];
        ulonglong2 p2 = sP[d][2];
        ulonglong2 p3 = sP[d][3];
        ulonglong2 p4 = sP[d][4];
        unsigned long long wk2[KS] = {p0.x, p0.y, p1.x, p1.y, p2.x,
                                      p2.y, p3.x, p3.y, p4.x};
        unsigned long long bd2 = p4.y;
        float w2 = sW2[d];

        // 4 independent packed 9-deep FMA chains (good ILP)
        #pragma unroll
        for (int p = 0; p < TPT / 2; p++) {
            unsigned long long h2 = bd2;
            #pragma unroll
            for (int k = 0; k < KS; k++)
                h2 = fma2(xp[2 * p + k], wk2[k], h2);
            float h0, h1;
            unpack2(h2, h0, h1);
            acc[2 * p]     = fmaf(fmaxf(h0, 0.f), w2, acc[2 * p]);
            acc[2 * p + 1] = fmaf(fmaxf(h1, 0.f), w2, acc[2 * p + 1]);
        }
    }

    float* yr = y + row * LEN + t0;
    #pragma unroll
    for (int t = 0; t < TPT; t++) yr[t] = acc[t] + bias2;
}

extern "C" void kernel_launch(void* const* d_in, const int* in_sizes, int n_in,
                              void* d_out, int out_size) {
    const float* x  = (const float*)d_in[0];
    const float* W1 = (const float*)d_in[1];
    const float* b1 = (const float*)d_in[2];
    const float* W2 = (const float*)d_in[3];
    const float* b2 = (const float*)d_in[4];
    float* y = (float*)d_out;
    simconv1d_kernel<<<ROWS * 2, TPB>>>(x, W1, b1, W2, b2, y);
}

// round 5
// speedup vs baseline: 1.2767x; 1.0539x over previous
#include <cuda_runtime.h>
#include <cstdint>

#define KS   9
#define HID  128
#define LEN  2048
#define ROWS 512       // B*H = 8*64
#define TPB  128
#define TPT  8         // outputs per thread
#define HALF_LEN 1024  // outputs per block (half a row)

typedef unsigned long long ull;

// ---- packed f32x2 helpers (sm_103a) ----
__device__ __forceinline__ ull pack2(float lo, float hi) {
    ull r;
    asm("mov.b64 %0, {%1,%2};" : "=l"(r) : "f"(lo), "f"(hi));
    return r;
}
__device__ __forceinline__ void unpack2(ull v, float& lo, float& hi) {
    asm("mov.b64 {%0,%1}, %2;" : "=f"(lo), "=f"(hi) : "l"(v));
}
__device__ __forceinline__ ull fma2(ull a, ull b, ull c) {
    ull d;
    asm("fma.rn.f32x2 %0, %1, %2, %3;" : "=l"(d) : "l"(a), "l"(b), "l"(c));
    return d;
}

__global__ __launch_bounds__(TPB, 5)
void simconv1d_kernel(const float* __restrict__ x,
                      const float* __restrict__ W1,   // [9][128] (k, d)
                      const float* __restrict__ b1,   // [128]
                      const float* __restrict__ W2,   // [128]
                      const float* __restrict__ b2,   // [1]
                      float* __restrict__ y) {
    // Per-d packed operand record, 16B-aligned, 6 x ulonglong2 = 12 u64 slots:
    // {w0,w1},{w2,w3},{w4,w5},{w6,w7},{w8,bias},{w2dup,pad}
    __shared__ ulonglong2 sP[HID][6];

    ull* sPu = reinterpret_cast<ull*>(sP);
    const int tid = threadIdx.x;

    for (int i = tid; i < KS * HID; i += TPB) {
        int k = i / HID;            // 0..8
        int d = i - k * HID;
        float w = W1[i];
        sPu[d * 12 + k] = pack2(w, w);
    }
    if (tid < HID) {
        float b = b1[tid];
        float w2 = W2[tid];
        sPu[tid * 12 + 9]  = pack2(b, b);
        sPu[tid * 12 + 10] = pack2(w2, w2);
        sPu[tid * 12 + 11] = 0ull;
    }
    __syncthreads();

    const int row  = blockIdx.x >> 1;
    const int half = blockIdx.x & 1;
    const float* xr = x + row * LEN;
    const int t0 = half * HALF_LEN + tid * TPT;   // first output position

    // Load the 16 x values covering outputs [t0, t0+8) with taps o-4..o+4.
    float xv[TPT + KS - 1];                // 16
    #pragma unroll
    for (int i = 0; i < TPT + KS - 1; i++) {
        int gi = t0 - 4 + i;
        xv[i] = (gi >= 0 && gi < LEN) ? __ldg(xr + gi) : 0.f;
    }

    // Pre-pack overlapping adjacent pairs: xp[i] = (xv[i], xv[i+1])
    ull xp[TPT + KS - 2];   // 15
    #pragma unroll
    for (int i = 0; i < TPT + KS - 2; i++) xp[i] = pack2(xv[i], xv[i + 1]);

    // Packed accumulators: acc2[p] holds outputs (2p, 2p+1)
    ull acc2[TPT / 2];
    #pragma unroll
    for (int p = 0; p < TPT / 2; p++) acc2[p] = 0ull;

    const float bias2 = b2[0];

    // Software-pipelined weight record: prefetch d+1 while computing d.
    ulonglong2 c0 = sP[0][0], c1 = sP[0][1], c2 = sP[0][2],
               c3 = sP[0][3], c4 = sP[0][4], c5 = sP[0][5];

    #pragma unroll 2
    for (int d = 0; d < HID; d++) {
        // prefetch next iteration's 6 broadcast LDS.128 (conflict-free)
        int dn = (d + 1) & (HID - 1);
        ulonglong2 n0 = sP[dn][0], n1 = sP[dn][1], n2 = sP[dn][2],
                   n3 = sP[dn][3], n4 = sP[dn][4], n5 = sP[dn][5];

        ull wk2[KS] = {c0.x, c0.y, c1.x, c1.y, c2.x,
                       c2.y, c3.x, c3.y, c4.x};
        ull bd2 = c4.y;
        ull w2d = c5.x;

        // 4 independent packed 9-deep FMA chains
        #pragma unroll
        for (int p = 0; p < TPT / 2; p++) {
            ull h2 = bd2;
            #pragma unroll
            for (int k = 0; k < KS; k++)
                h2 = fma2(xp[2 * p + k], wk2[k], h2);
            float h0, h1;
            unpack2(h2, h0, h1);                  // virtual (pair alias)
            h0 = fmaxf(h0, 0.f);                  // FMNMX (alu pipe)
            h1 = fmaxf(h1, 0.f);
            acc2[p] = fma2(pack2(h0, h1), w2d, acc2[p]);  // packed accumulate
        }

        c0 = n0; c1 = n1; c2 = n2; c3 = n3; c4 = n4; c5 = n5;
    }

    float* yr = y + row * LEN + t0;
    #pragma unroll
    for (int p = 0; p < TPT / 2; p++) {
        float a0, a1;
        unpack2(acc2[p], a0, a1);
        yr[2 * p]     = a0 + bias2;
        yr[2 * p + 1] = a1 + bias2;
    }
}

extern "C" void kernel_launch(void* const* d_in, const int* in_sizes, int n_in,
                              void* d_out, int out_size) {
    const float* x  = (const float*)d_in[0];
    const float* W1 = (const float*)d_in[1];
    const float* b1 = (const float*)d_in[2];
    const float* W2 = (const float*)d_in[3];
    const float* b2 = (const float*)d_in[4];
    float* y = (float*)d_out;
    simconv1d_kernel<<<ROWS * 2, TPB>>>(x, W1, b1, W2, b2, y);
}